// round 1
// baseline (speedup 1.0000x reference)
#include <cuda_runtime.h>
#include <math.h>

#define NB     4096
#define DIN    256
#define NH1    512
#define NH2    512
#define NDOUT  256
#define BN_EPS 1e-5f

// -------- scratch (device globals; no allocation) --------
__device__ float g_h[NB * NH1];        // linear output (pre-BN)
__device__ float g_y2[NB * NH2];       // KAN-2 output
__device__ float g_c1[NH1 * NB];       // cos(t), layout [i][n]
__device__ float g_s1[NH1 * NB];       // sin(t), layout [i][n]
__device__ float g_c2[NH2 * NB];       // cos(y2), layout [i][n]
__device__ float g_s2[NH2 * NB];       // sin(y2), layout [i][n]
__device__ float g_stats[2];           // sum, sumsq
__device__ float g_bn[2];              // scale, shift

__global__ void k_init() {
    g_stats[0] = 0.f;
    g_stats[1] = 0.f;
}

// -------- Linear: h = x @ W1^T + b1, plus BN partial sums --------
// 4096x512, K=256. BM=BN=64, BK=16, 256 threads, 4x4 per thread.
__global__ void k_linear(const float* __restrict__ x, const float* __restrict__ W1,
                         const float* __restrict__ b1) {
    __shared__ float As[16][68];
    __shared__ float Bs[16][68];
    int tid = threadIdx.x;
    int tx = tid & 15, ty = tid >> 4;
    int bm = blockIdx.y * 64, bn = blockIdx.x * 64;

    float acc[4][4] = {};
    for (int k0 = 0; k0 < DIN; k0 += 16) {
        #pragma unroll
        for (int l = tid; l < 1024; l += 256) {
            int m = l >> 4, k = l & 15;
            As[k][m] = x[(bm + m) * DIN + k0 + k];
            Bs[k][m] = W1[(bn + m) * DIN + k0 + k];
        }
        __syncthreads();
        #pragma unroll
        for (int k = 0; k < 16; k++) {
            float a[4], b[4];
            *(float4*)&a[0] = *(const float4*)&As[k][ty * 4];
            *(float4*)&b[0] = *(const float4*)&Bs[k][tx * 4];
            #pragma unroll
            for (int r = 0; r < 4; r++)
                #pragma unroll
                for (int c = 0; c < 4; c++)
                    acc[r][c] = fmaf(a[r], b[c], acc[r][c]);
        }
        __syncthreads();
    }

    float s = 0.f, s2 = 0.f;
    #pragma unroll
    for (int r = 0; r < 4; r++) {
        int row = bm + ty * 4 + r;
        #pragma unroll
        for (int c = 0; c < 4; c++) {
            int col = bn + tx * 4 + c;
            float v = acc[r][c] + b1[col];
            g_h[row * NH1 + col] = v;
            s += v;
            s2 += v * v;
        }
    }
    // block reduce -> 2 atomics
    #pragma unroll
    for (int off = 16; off; off >>= 1) {
        s  += __shfl_down_sync(0xFFFFFFFFu, s, off);
        s2 += __shfl_down_sync(0xFFFFFFFFu, s2, off);
    }
    __shared__ float ws[8], ws2[8];
    int wid = tid >> 5, lane = tid & 31;
    if (lane == 0) { ws[wid] = s; ws2[wid] = s2; }
    __syncthreads();
    if (tid == 0) {
        float ts = 0.f, ts2 = 0.f;
        #pragma unroll
        for (int w = 0; w < 8; w++) { ts += ws[w]; ts2 += ws2[w]; }
        atomicAdd(&g_stats[0], ts);
        atomicAdd(&g_stats[1], ts2);
    }
}

// -------- BN finalize: scale/shift scalars --------
__global__ void k_bn(const float* __restrict__ gamma, const float* __restrict__ beta) {
    float n = (float)(NB * NH1);
    float mean = g_stats[0] / n;
    float var = g_stats[1] / n - mean * mean;
    float inv = rsqrtf(var + BN_EPS);
    float sc = gamma[0] * inv;
    g_bn[0] = sc;
    g_bn[1] = beta[0] - mean * sc;
}

// -------- sincos precompute (layer 2 input): BN + ReLU fused, transpose to [i][n] --------
__global__ void k_cs1() {
    int idx = blockIdx.x * 256 + threadIdx.x;   // idx = i*NB + n
    int i = idx >> 12;
    int n = idx & (NB - 1);
    float t = fmaf(g_h[n * NH1 + i], g_bn[0], g_bn[1]);
    t = fmaxf(t, 0.f);
    float sv, cv;
    sincosf(t, &sv, &cv);
    g_c1[idx] = cv;
    g_s1[idx] = sv;
}

// -------- sincos precompute (layer 3 input) --------
__global__ void k_cs2() {
    int idx = blockIdx.x * 256 + threadIdx.x;
    int i = idx >> 12;
    int n = idx & (NB - 1);
    float t = g_y2[n * NH2 + i];
    float sv, cv;
    sincosf(t, &sv, &cv);
    g_c2[idx] = cv;
    g_s2[idx] = sv;
}

// -------- Fourier-KAN layer as fused GEMM --------
// out[n,o] = sum_i sum_g cos((g+1)t) * C0[o,i,g] + sin((g+1)t) * C1[o,i,g] + bias[o]
// BM=128, BN=64, 256 threads, 8x4 per thread. Basis generated per-tile via rotation recurrence.
template <int G, int NIN, int NOUT, bool FINAL>
__global__ void k_kan(const float* __restrict__ coeffs, const float* __restrict__ bias,
                      float* __restrict__ dout) {
    constexpr int KK = 2 * G;
    __shared__ float As[KK][132];   // [k][m]  (cos block then sin block)
    __shared__ float Bs[KK][68];    // [k][o]
    const float* __restrict__ cb = FINAL ? g_c2 : g_c1;
    const float* __restrict__ sb = FINAL ? g_s2 : g_s1;
    float* outp = FINAL ? dout : g_y2;

    int tid = threadIdx.x;
    int tx = tid & 15, ty = tid >> 4;
    int bm = blockIdx.y * 128, bn = blockIdx.x * 64;

    float acc[8][4] = {};

    for (int i = 0; i < NIN; i++) {
        // basis generation: 128 threads, one row each
        if (tid < 128) {
            int n = bm + tid;
            float c1 = cb[i * NB + n];
            float s1 = sb[i * NB + n];
            float ck = c1, sk = s1;
            As[0][tid] = ck;
            As[G][tid] = sk;
            #pragma unroll
            for (int g = 1; g < G; g++) {
                float cn = ck * c1 - sk * s1;
                float sn = sk * c1 + ck * s1;
                ck = cn; sk = sn;
                As[g][tid] = ck;
                As[G + g][tid] = sk;
            }
        }
        // coeff tile load
        #pragma unroll
        for (int l = tid; l < KK * 64; l += 256) {
            int k = l % KK, o = l / KK;
            int p = k / G, g = k - p * G;
            Bs[k][o] = coeffs[(((size_t)p * NOUT + bn + o) * NIN + i) * G + g];
        }
        __syncthreads();

        #pragma unroll
        for (int k = 0; k < KK; k++) {
            float a[8], b[4];
            *(float4*)&a[0] = *(const float4*)&As[k][ty * 8];
            *(float4*)&a[4] = *(const float4*)&As[k][ty * 8 + 4];
            *(float4*)&b[0] = *(const float4*)&Bs[k][tx * 4];
            #pragma unroll
            for (int r = 0; r < 8; r++)
                #pragma unroll
                for (int c = 0; c < 4; c++)
                    acc[r][c] = fmaf(a[r], b[c], acc[r][c]);
        }
        __syncthreads();
    }

    #pragma unroll
    for (int r = 0; r < 8; r++) {
        int row = bm + ty * 8 + r;
        #pragma unroll
        for (int c = 0; c < 4; c++) {
            int col = bn + tx * 4 + c;
            outp[(size_t)row * NOUT + col] = acc[r][c] + bias[col];
        }
    }
}

// -------- softmax over 256 logits, one block per row (in-place on d_out) --------
__global__ void k_softmax(float* __restrict__ out) {
    __shared__ float red[256];
    int n = blockIdx.x, t = threadIdx.x;
    float v = out[(size_t)n * NDOUT + t];
    red[t] = v;
    __syncthreads();
    #pragma unroll
    for (int s = 128; s > 0; s >>= 1) {
        if (t < s) red[t] = fmaxf(red[t], red[t + s]);
        __syncthreads();
    }
    float mx = red[0];
    __syncthreads();
    float e = expf(v - mx);
    red[t] = e;
    __syncthreads();
    #pragma unroll
    for (int s = 128; s > 0; s >>= 1) {
        if (t < s) red[t] += red[t + s];
        __syncthreads();
    }
    out[(size_t)n * NDOUT + t] = e / red[0];
}

extern "C" void kernel_launch(void* const* d_in, const int* in_sizes, int n_in,
                              void* d_out, int out_size) {
    const float* x       = (const float*)d_in[0];
    const float* W1      = (const float*)d_in[1];
    const float* b1      = (const float*)d_in[2];
    const float* gamma   = (const float*)d_in[3];
    const float* beta    = (const float*)d_in[4];
    const float* coeffs2 = (const float*)d_in[5];
    const float* bias2   = (const float*)d_in[6];
    const float* coeffs3 = (const float*)d_in[7];
    const float* bias3   = (const float*)d_in[8];
    float* out = (float*)d_out;

    k_init<<<1, 1>>>();
    k_linear<<<dim3(NH1 / 64, NB / 64), 256>>>(x, W1, b1);
    k_bn<<<1, 1>>>(gamma, beta);
    k_cs1<<<(NH1 * NB) / 256, 256>>>();
    k_kan<16, NH1, NH2, false><<<dim3(NH2 / 64, NB / 128), 256>>>(coeffs2, bias2, nullptr);
    k_cs2<<<(NH2 * NB) / 256, 256>>>();
    k_kan<8, NH2, NDOUT, true><<<dim3(NDOUT / 64, NB / 128), 256>>>(coeffs3, bias3, out);
    k_softmax<<<NB, 256>>>(out);
}

// round 15
// speedup vs baseline: 1.2343x; 1.2343x over previous
#include <cuda_runtime.h>
#include <math.h>
#include <cstdint>

#define NB     4096
#define DIN    256
#define NH1    512
#define NH2    512
#define NDOUT  256
#define BN_EPS 1e-5f

// ---------------- scratch (device globals; no allocation) ----------------
__device__ float g_h[NB * NH1];        // linear output (pre-BN)
__device__ float g_c1[NH1 * NB];       // cos(t), layout [i][n]
__device__ float g_s1[NH1 * NB];       // sin(t), layout [i][n]
__device__ float g_c2[NH2 * NB];       // cos(y2), layout [o][n]
__device__ float g_s2[NH2 * NB];       // sin(y2), layout [o][n]
__device__ float g_stats[2];           // sum, sumsq
__device__ float g_bn[2];              // scale, shift

// packed f32x2 helpers
__device__ __forceinline__ void fma2(unsigned long long& d,
                                     unsigned long long a, unsigned long long b) {
    asm("fma.rn.f32x2 %0, %1, %2, %0;" : "+l"(d) : "l"(a), "l"(b));
}
__device__ __forceinline__ unsigned long long splat2(float x) {
    unsigned long long r;
    asm("mov.b64 %0, {%1, %2};" : "=l"(r) : "f"(x), "f"(x));
    return r;
}
__device__ __forceinline__ void unpack2(float& lo, float& hi, unsigned long long v) {
    asm("mov.b64 {%0, %1}, %2;" : "=f"(lo), "=f"(hi) : "l"(v));
}

__global__ void k_init() {
    g_stats[0] = 0.f;
    g_stats[1] = 0.f;
}

// -------- Linear: h = x @ W1^T + b1, plus BN partial sums (round-1 validated) --------
__global__ void k_linear(const float* __restrict__ x, const float* __restrict__ W1,
                         const float* __restrict__ b1) {
    __shared__ float As[16][68];
    __shared__ float Bs[16][68];
    int tid = threadIdx.x;
    int tx = tid & 15, ty = tid >> 4;
    int bm = blockIdx.y * 64, bn = blockIdx.x * 64;

    float acc[4][4] = {};
    for (int k0 = 0; k0 < DIN; k0 += 16) {
        #pragma unroll
        for (int l = tid; l < 1024; l += 256) {
            int m = l >> 4, k = l & 15;
            As[k][m] = x[(bm + m) * DIN + k0 + k];
            Bs[k][m] = W1[(bn + m) * DIN + k0 + k];
        }
        __syncthreads();
        #pragma unroll
        for (int k = 0; k < 16; k++) {
            float a[4], b[4];
            *(float4*)&a[0] = *(const float4*)&As[k][ty * 4];
            *(float4*)&b[0] = *(const float4*)&Bs[k][tx * 4];
            #pragma unroll
            for (int r = 0; r < 4; r++)
                #pragma unroll
                for (int c = 0; c < 4; c++)
                    acc[r][c] = fmaf(a[r], b[c], acc[r][c]);
        }
        __syncthreads();
    }

    float s = 0.f, s2 = 0.f;
    #pragma unroll
    for (int r = 0; r < 4; r++) {
        int row = bm + ty * 4 + r;
        #pragma unroll
        for (int c = 0; c < 4; c++) {
            int col = bn + tx * 4 + c;
            float v = acc[r][c] + b1[col];
            g_h[row * NH1 + col] = v;
            s += v;
            s2 += v * v;
        }
    }
    #pragma unroll
    for (int off = 16; off; off >>= 1) {
        s  += __shfl_down_sync(0xFFFFFFFFu, s, off);
        s2 += __shfl_down_sync(0xFFFFFFFFu, s2, off);
    }
    __shared__ float ws[8], ws2[8];
    int wid = tid >> 5, lane = tid & 31;
    if (lane == 0) { ws[wid] = s; ws2[wid] = s2; }
    __syncthreads();
    if (tid == 0) {
        float ts = 0.f, ts2 = 0.f;
        #pragma unroll
        for (int w = 0; w < 8; w++) { ts += ws[w]; ts2 += ws2[w]; }
        atomicAdd(&g_stats[0], ts);
        atomicAdd(&g_stats[1], ts2);
    }
}

__global__ void k_bn(const float* __restrict__ gamma, const float* __restrict__ beta) {
    float n = (float)(NB * NH1);
    float mean = g_stats[0] / n;
    float var = g_stats[1] / n - mean * mean;
    float inv = rsqrtf(var + BN_EPS);
    float sc = gamma[0] * inv;
    g_bn[0] = sc;
    g_bn[1] = beta[0] - mean * sc;
}

// BN + ReLU + sincos, transposed to [i][n] (round-1 validated)
__global__ void k_cs1() {
    int idx = blockIdx.x * 256 + threadIdx.x;
    int i = idx >> 12;
    int n = idx & (NB - 1);
    float t = fmaf(g_h[n * NH1 + i], g_bn[0], g_bn[1]);
    t = fmaxf(t, 0.f);
    float sv, cv;
    sincosf(t, &sv, &cv);
    g_c1[idx] = cv;
    g_s1[idx] = sv;
}

// -------- Fourier-KAN GEMM, f32x2-packed FMA inner loop --------
// Structure identical to round-1 validated k_kan; only the MAC loop is packed
// (row-pairs in one f32x2 lane; accumulation order per output unchanged) and
// the non-FINAL epilogue fuses bias + sincos + transposed write to g_c2/g_s2.
template <int G, int NIN, int NOUT, bool FINAL>
__global__ void __launch_bounds__(256, 2)
k_kan(const float* __restrict__ coeffs, const float* __restrict__ bias,
      float* __restrict__ dout) {
    constexpr int KK = 2 * G;
    __shared__ float As[KK][132];   // [k][m]  cos block then sin block
    __shared__ float Bs[KK][68];    // [k][o]
    const float* __restrict__ cb = FINAL ? g_c2 : g_c1;
    const float* __restrict__ sb = FINAL ? g_s2 : g_s1;

    int tid = threadIdx.x;
    int tx = tid & 15, ty = tid >> 4;
    int bm = blockIdx.y * 128, bn = blockIdx.x * 64;

    unsigned long long acc2[4][4] = {};   // [m-pair][c], f32x2 packed {row, row+1}

    for (int i = 0; i < NIN; i++) {
        // basis generation: 128 threads, one batch-row each (validated)
        if (tid < 128) {
            int n = bm + tid;
            float c1 = cb[(size_t)i * NB + n];
            float s1 = sb[(size_t)i * NB + n];
            float ck = c1, sk = s1;
            As[0][tid] = ck;
            As[G][tid] = sk;
            #pragma unroll
            for (int g = 1; g < G; g++) {
                float cn = ck * c1 - sk * s1;
                float sn = sk * c1 + ck * s1;
                ck = cn; sk = sn;
                As[g][tid] = ck;
                As[G + g][tid] = sk;
            }
        }
        // coeff tile load (validated indexing)
        #pragma unroll
        for (int l = tid; l < KK * 64; l += 256) {
            int k = l % KK, o = l / KK;
            int p = k / G, g = k - p * G;
            Bs[k][o] = coeffs[(((size_t)p * NOUT + bn + o) * NIN + i) * G + g];
        }
        __syncthreads();

        #pragma unroll
        for (int k = 0; k < KK; k++) {
            unsigned long long a2[4], b2[4];
            const float* arow = &As[k][ty * 8];
            a2[0] = *(const unsigned long long*)(arow + 0);
            a2[1] = *(const unsigned long long*)(arow + 2);
            a2[2] = *(const unsigned long long*)(arow + 4);
            a2[3] = *(const unsigned long long*)(arow + 6);
            float b[4];
            *(float4*)&b[0] = *(const float4*)&Bs[k][tx * 4];
            #pragma unroll
            for (int c = 0; c < 4; c++) b2[c] = splat2(b[c]);
            #pragma unroll
            for (int r2 = 0; r2 < 4; r2++)
                #pragma unroll
                for (int c = 0; c < 4; c++)
                    fma2(acc2[r2][c], a2[r2], b2[c]);
        }
        __syncthreads();
    }

    // epilogue
    #pragma unroll
    for (int r2 = 0; r2 < 4; r2++) {
        int row = bm + ty * 8 + 2 * r2;
        #pragma unroll
        for (int c = 0; c < 4; c++) {
            int col = bn + tx * 4 + c;
            float vlo, vhi;
            unpack2(vlo, vhi, acc2[r2][c]);
            float ylo = vlo + bias[col];
            float yhi = vhi + bias[col];
            if (FINAL) {
                dout[(size_t)row * NOUT + col] = ylo;
                dout[(size_t)(row + 1) * NOUT + col] = yhi;
            } else {
                float sv, cv;
                sincosf(ylo, &sv, &cv);
                g_c2[(size_t)col * NB + row] = cv;
                g_s2[(size_t)col * NB + row] = sv;
                sincosf(yhi, &sv, &cv);
                g_c2[(size_t)col * NB + row + 1] = cv;
                g_s2[(size_t)col * NB + row + 1] = sv;
            }
        }
    }
}

// -------- softmax (round-1 validated) --------
__global__ void k_softmax(float* __restrict__ out) {
    __shared__ float red[256];
    int n = blockIdx.x, t = threadIdx.x;
    float v = out[(size_t)n * NDOUT + t];
    red[t] = v;
    __syncthreads();
    #pragma unroll
    for (int s = 128; s > 0; s >>= 1) {
        if (t < s) red[t] = fmaxf(red[t], red[t + s]);
        __syncthreads();
    }
    float mx = red[0];
    __syncthreads();
    float e = expf(v - mx);
    red[t] = e;
    __syncthreads();
    #pragma unroll
    for (int s = 128; s > 0; s >>= 1) {
        if (t < s) red[t] += red[t + s];
        __syncthreads();
    }
    out[(size_t)n * NDOUT + t] = e / red[0];
}

extern "C" void kernel_launch(void* const* d_in, const int* in_sizes, int n_in,
                              void* d_out, int out_size) {
    const float* x       = (const float*)d_in[0];
    const float* W1      = (const float*)d_in[1];
    const float* b1      = (const float*)d_in[2];
    const float* gamma   = (const float*)d_in[3];
    const float* beta    = (const float*)d_in[4];
    const float* coeffs2 = (const float*)d_in[5];
    const float* bias2   = (const float*)d_in[6];
    const float* coeffs3 = (const float*)d_in[7];
    const float* bias3   = (const float*)d_in[8];
    float* out = (float*)d_out;

    k_init<<<1, 1>>>();
    k_linear<<<dim3(NH1 / 64, NB / 64), 256>>>(x, W1, b1);
    k_bn<<<1, 1>>>(gamma, beta);
    k_cs1<<<(NH1 * NB) / 256, 256>>>();
    k_kan<16, NH1, NH2, false><<<dim3(NH2 / 64, NB / 128), 256>>>(coeffs2, bias2, nullptr);
    k_kan<8, NH2, NDOUT, true><<<dim3(NDOUT / 64, NB / 128), 256>>>(coeffs3, bias3, out);
    k_softmax<<<NB, 256>>>(out);
}

// round 16
// speedup vs baseline: 1.9144x; 1.5509x over previous
#include <cuda_runtime.h>
#include <math.h>
#include <cstdint>

#define NB     4096
#define DIN    256
#define NH1    512
#define NH2    512
#define NDOUT  256
#define BN_EPS 1e-5f

// ---------------- scratch (device globals; no allocation) ----------------
__device__ float g_h[NB * NH1];        // linear output (pre-BN)
__device__ float g_c1[NH1 * NB];       // cos(t), layout [i][n]
__device__ float g_s1[NH1 * NB];       // sin(t), layout [i][n]
__device__ float g_c2[NH2 * NB];       // cos(y2), layout [o][n]
__device__ float g_s2[NH2 * NB];       // sin(y2), layout [o][n]
__device__ float g_stats[2];           // sum, sumsq
__device__ float g_bn[2];              // scale, shift

// packed f32x2 helpers
__device__ __forceinline__ void fma2(unsigned long long& d,
                                     unsigned long long a, unsigned long long b) {
    asm("fma.rn.f32x2 %0, %1, %2, %0;" : "+l"(d) : "l"(a), "l"(b));
}
__device__ __forceinline__ unsigned long long splat2(float x) {
    unsigned long long r;
    asm("mov.b64 %0, {%1, %2};" : "=l"(r) : "f"(x), "f"(x));
    return r;
}
__device__ __forceinline__ void unpack2(float& lo, float& hi, unsigned long long v) {
    asm("mov.b64 {%0, %1}, %2;" : "=f"(lo), "=f"(hi) : "l"(v));
}

__global__ void k_init() {
    g_stats[0] = 0.f;
    g_stats[1] = 0.f;
}

// -------- Linear: h = x @ W1^T + b1, plus BN partial sums (validated) --------
__global__ void k_linear(const float* __restrict__ x, const float* __restrict__ W1,
                         const float* __restrict__ b1) {
    __shared__ float As[16][68];
    __shared__ float Bs[16][68];
    int tid = threadIdx.x;
    int tx = tid & 15, ty = tid >> 4;
    int bm = blockIdx.y * 64, bn = blockIdx.x * 64;

    float acc[4][4] = {};
    for (int k0 = 0; k0 < DIN; k0 += 16) {
        #pragma unroll
        for (int l = tid; l < 1024; l += 256) {
            int m = l >> 4, k = l & 15;
            As[k][m] = x[(bm + m) * DIN + k0 + k];
            Bs[k][m] = W1[(bn + m) * DIN + k0 + k];
        }
        __syncthreads();
        #pragma unroll
        for (int k = 0; k < 16; k++) {
            float a[4], b[4];
            *(float4*)&a[0] = *(const float4*)&As[k][ty * 4];
            *(float4*)&b[0] = *(const float4*)&Bs[k][tx * 4];
            #pragma unroll
            for (int r = 0; r < 4; r++)
                #pragma unroll
                for (int c = 0; c < 4; c++)
                    acc[r][c] = fmaf(a[r], b[c], acc[r][c]);
        }
        __syncthreads();
    }

    float s = 0.f, s2 = 0.f;
    #pragma unroll
    for (int r = 0; r < 4; r++) {
        int row = bm + ty * 4 + r;
        #pragma unroll
        for (int c = 0; c < 4; c++) {
            int col = bn + tx * 4 + c;
            float v = acc[r][c] + b1[col];
            g_h[row * NH1 + col] = v;
            s += v;
            s2 += v * v;
        }
    }
    #pragma unroll
    for (int off = 16; off; off >>= 1) {
        s  += __shfl_down_sync(0xFFFFFFFFu, s, off);
        s2 += __shfl_down_sync(0xFFFFFFFFu, s2, off);
    }
    __shared__ float ws[8], ws2[8];
    int wid = tid >> 5, lane = tid & 31;
    if (lane == 0) { ws[wid] = s; ws2[wid] = s2; }
    __syncthreads();
    if (tid == 0) {
        float ts = 0.f, ts2 = 0.f;
        #pragma unroll
        for (int w = 0; w < 8; w++) { ts += ws[w]; ts2 += ws2[w]; }
        atomicAdd(&g_stats[0], ts);
        atomicAdd(&g_stats[1], ts2);
    }
}

__global__ void k_bn(const float* __restrict__ gamma, const float* __restrict__ beta) {
    float n = (float)(NB * NH1);
    float mean = g_stats[0] / n;
    float var = g_stats[1] / n - mean * mean;
    float inv = rsqrtf(var + BN_EPS);
    float sc = gamma[0] * inv;
    g_bn[0] = sc;
    g_bn[1] = beta[0] - mean * sc;
}

// BN + ReLU + sincos, transposed to [i][n] (validated)
__global__ void k_cs1() {
    int idx = blockIdx.x * 256 + threadIdx.x;
    int i = idx >> 12;
    int n = idx & (NB - 1);
    float t = fmaf(g_h[n * NH1 + i], g_bn[0], g_bn[1]);
    t = fmaxf(t, 0.f);
    float sv, cv;
    sincosf(t, &sv, &cv);
    g_c1[idx] = cv;
    g_s1[idx] = sv;
}

// -------- KAN2: f32x2 FMA GEMM, 128x64 tile, fused sincos epilogue (R15 validated) --------
__global__ void __launch_bounds__(256, 2)
k_kan2(const float* __restrict__ coeffs, const float* __restrict__ bias) {
    constexpr int G = 16;
    constexpr int NIN = NH1, NOUT = NH2;
    constexpr int KK = 2 * G;
    __shared__ float As[KK][132];
    __shared__ float Bs[KK][68];

    int tid = threadIdx.x;
    int tx = tid & 15, ty = tid >> 4;
    int bm = blockIdx.y * 128, bn = blockIdx.x * 64;

    unsigned long long acc2[4][4] = {};

    for (int i = 0; i < NIN; i++) {
        if (tid < 128) {
            int n = bm + tid;
            float c1 = g_c1[(size_t)i * NB + n];
            float s1 = g_s1[(size_t)i * NB + n];
            float ck = c1, sk = s1;
            As[0][tid] = ck;
            As[G][tid] = sk;
            #pragma unroll
            for (int g = 1; g < G; g++) {
                float cn = ck * c1 - sk * s1;
                float sn = sk * c1 + ck * s1;
                ck = cn; sk = sn;
                As[g][tid] = ck;
                As[G + g][tid] = sk;
            }
        }
        #pragma unroll
        for (int l = tid; l < KK * 64; l += 256) {
            int k = l % KK, o = l / KK;
            int p = k / G, g = k - p * G;
            Bs[k][o] = coeffs[(((size_t)p * NOUT + bn + o) * NIN + i) * G + g];
        }
        __syncthreads();

        #pragma unroll
        for (int k = 0; k < KK; k++) {
            unsigned long long a2[4], b2[4];
            const float* arow = &As[k][ty * 8];
            a2[0] = *(const unsigned long long*)(arow + 0);
            a2[1] = *(const unsigned long long*)(arow + 2);
            a2[2] = *(const unsigned long long*)(arow + 4);
            a2[3] = *(const unsigned long long*)(arow + 6);
            float b[4];
            *(float4*)&b[0] = *(const float4*)&Bs[k][tx * 4];
            #pragma unroll
            for (int c = 0; c < 4; c++) b2[c] = splat2(b[c]);
            #pragma unroll
            for (int r2 = 0; r2 < 4; r2++)
                #pragma unroll
                for (int c = 0; c < 4; c++)
                    fma2(acc2[r2][c], a2[r2], b2[c]);
        }
        __syncthreads();
    }

    #pragma unroll
    for (int r2 = 0; r2 < 4; r2++) {
        int row = bm + ty * 8 + 2 * r2;
        #pragma unroll
        for (int c = 0; c < 4; c++) {
            int col = bn + tx * 4 + c;
            float vlo, vhi;
            unpack2(vlo, vhi, acc2[r2][c]);
            float ylo = vlo + bias[col];
            float yhi = vhi + bias[col];
            float sv, cv;
            sincosf(ylo, &sv, &cv);
            g_c2[(size_t)col * NB + row] = cv;
            g_s2[(size_t)col * NB + row] = sv;
            sincosf(yhi, &sv, &cv);
            g_c2[(size_t)col * NB + row + 1] = cv;
            g_s2[(size_t)col * NB + row + 1] = sv;
        }
    }
}

// -------- KAN3: f32x2 FMA GEMM, 64x64 tile for full-chip occupancy --------
// grid (NDOUT/64, NB/64) = 256 CTAs -> 2/SM on all 148 SMs.
// Thread tile: 4 rows (2 f32x2 pairs) x 4 cols.
__global__ void __launch_bounds__(256, 2)
k_kan3(const float* __restrict__ coeffs, const float* __restrict__ bias,
       float* __restrict__ dout) {
    constexpr int G = 8;
    constexpr int NIN = NH2, NOUT = NDOUT;
    constexpr int KK = 2 * G;
    __shared__ float As[KK][68];    // [k][m], 64 rows
    __shared__ float Bs[KK][68];    // [k][o]

    int tid = threadIdx.x;
    int tx = tid & 15, ty = tid >> 4;
    int bm = blockIdx.y * 64, bn = blockIdx.x * 64;

    unsigned long long acc2[2][4] = {};

    for (int i = 0; i < NIN; i++) {
        // basis: 64 rows by threads 0-63
        if (tid < 64) {
            int n = bm + tid;
            float c1 = g_c2[(size_t)i * NB + n];
            float s1 = g_s2[(size_t)i * NB + n];
            float ck = c1, sk = s1;
            As[0][tid] = ck;
            As[G][tid] = sk;
            #pragma unroll
            for (int g = 1; g < G; g++) {
                float cn = ck * c1 - sk * s1;
                float sn = sk * c1 + ck * s1;
                ck = cn; sk = sn;
                As[g][tid] = ck;
                As[G + g][tid] = sk;
            }
        }
        // coeff tile: KK*64 = 1024 floats, 4 per thread (validated indexing)
        #pragma unroll
        for (int l = tid; l < KK * 64; l += 256) {
            int k = l % KK, o = l / KK;
            int p = k / G, g = k - p * G;
            Bs[k][o] = coeffs[(((size_t)p * NOUT + bn + o) * NIN + i) * G + g];
        }
        __syncthreads();

        #pragma unroll
        for (int k = 0; k < KK; k++) {
            unsigned long long a2[2], b2[4];
            const float* arow = &As[k][ty * 4];
            a2[0] = *(const unsigned long long*)(arow + 0);
            a2[1] = *(const unsigned long long*)(arow + 2);
            float b[4];
            *(float4*)&b[0] = *(const float4*)&Bs[k][tx * 4];
            #pragma unroll
            for (int c = 0; c < 4; c++) b2[c] = splat2(b[c]);
            #pragma unroll
            for (int r2 = 0; r2 < 2; r2++)
                #pragma unroll
                for (int c = 0; c < 4; c++)
                    fma2(acc2[r2][c], a2[r2], b2[c]);
        }
        __syncthreads();
    }

    #pragma unroll
    for (int r2 = 0; r2 < 2; r2++) {
        int row = bm + ty * 4 + 2 * r2;
        #pragma unroll
        for (int c = 0; c < 4; c++) {
            int col = bn + tx * 4 + c;
            float vlo, vhi;
            unpack2(vlo, vhi, acc2[r2][c]);
            dout[(size_t)row * NOUT + col] = vlo + bias[col];
            dout[(size_t)(row + 1) * NOUT + col] = vhi + bias[col];
        }
    }
}

// -------- softmax (validated) --------
__global__ void k_softmax(float* __restrict__ out) {
    __shared__ float red[256];
    int n = blockIdx.x, t = threadIdx.x;
    float v = out[(size_t)n * NDOUT + t];
    red[t] = v;
    __syncthreads();
    #pragma unroll
    for (int s = 128; s > 0; s >>= 1) {
        if (t < s) red[t] = fmaxf(red[t], red[t + s]);
        __syncthreads();
    }
    float mx = red[0];
    __syncthreads();
    float e = expf(v - mx);
    red[t] = e;
    __syncthreads();
    #pragma unroll
    for (int s = 128; s > 0; s >>= 1) {
        if (t < s) red[t] += red[t + s];
        __syncthreads();
    }
    out[(size_t)n * NDOUT + t] = e / red[0];
}

extern "C" void kernel_launch(void* const* d_in, const int* in_sizes, int n_in,
                              void* d_out, int out_size) {
    const float* x       = (const float*)d_in[0];
    const float* W1      = (const float*)d_in[1];
    const float* b1      = (const float*)d_in[2];
    const float* gamma   = (const float*)d_in[3];
    const float* beta    = (const float*)d_in[4];
    const float* coeffs2 = (const float*)d_in[5];
    const float* bias2   = (const float*)d_in[6];
    const float* coeffs3 = (const float*)d_in[7];
    const float* bias3   = (const float*)d_in[8];
    float* out = (float*)d_out;

    k_init<<<1, 1>>>();
    k_linear<<<dim3(NH1 / 64, NB / 64), 256>>>(x, W1, b1);
    k_bn<<<1, 1>>>(gamma, beta);
    k_cs1<<<(NH1 * NB) / 256, 256>>>();
    k_kan2<<<dim3(NH2 / 64, NB / 128), 256>>>(coeffs2, bias2);
    k_kan3<<<dim3(NDOUT / 64, NB / 64), 256>>>(coeffs3, bias3, out);
    k_softmax<<<NB, 256>>>(out);
}